// round 2
// baseline (speedup 1.0000x reference)
#include <cuda_runtime.h>

#define FNUM 50
#define DDIM 16
#define ADIM 32
#define NP   1225            // F*(F-1)/2
#define NT   (2 * NP)        // tasks: (pair, half-of-A)
#define TPB  256
#define NIT  ((NT + TPB - 1) / TPB)   // 10

// ---- packed f32x2 helpers (ptxas will not auto-fuse; must be inline PTX) ----
__device__ __forceinline__ unsigned long long pk2(float lo, float hi) {
    unsigned long long r;
    asm("mov.b64 %0, {%1, %2};" : "=l"(r) : "f"(lo), "f"(hi));
    return r;
}
__device__ __forceinline__ unsigned long long fma2(unsigned long long a,
                                                   unsigned long long b,
                                                   unsigned long long c) {
    unsigned long long d;
    asm("fma.rn.f32x2 %0, %1, %2, %3;" : "=l"(d) : "l"(a), "l"(b), "l"(c));
    return d;
}
__device__ __forceinline__ float2 upk2(unsigned long long v) {
    float lo, hi;
    asm("mov.b64 {%0, %1}, %2;" : "=f"(lo), "=f"(hi) : "l"(v));
    return make_float2(lo, hi);
}

__global__ __launch_bounds__(TPB, 3) void afm_kernel(
    const float* __restrict__ feat,   // [B, F, D]
    const float* __restrict__ Wg,     // [D, A]
    const float* __restrict__ hg,     // [A]
    const float* __restrict__ pvg,    // [D]
    float* __restrict__ out)          // [B]
{
    __shared__ __align__(16) float s_e[FNUM * DDIM];   // 800 floats
    __shared__ __align__(16) float s_W[DDIM * ADIM];   // 512 floats, row-major
    __shared__ __align__(16) float s_h[ADIM];
    __shared__ float s_score[NP];
    __shared__ float s_t[NP];
    __shared__ unsigned char s_row[NP];
    __shared__ unsigned char s_col[NP];
    __shared__ float s_red[24];

    const int tid = threadIdx.x;
    const int b   = blockIdx.x;

    // ---- cooperative loads into SMEM ----
    {
        const float4* src = (const float4*)(feat + (size_t)b * (FNUM * DDIM));
        float4* dst = (float4*)s_e;
        #pragma unroll 1
        for (int i = tid; i < (FNUM * DDIM) / 4; i += TPB) dst[i] = src[i];

        const float4* ws = (const float4*)Wg;
        float4* wd = (float4*)s_W;
        if (tid < (DDIM * ADIM) / 4) wd[tid] = ws[tid];

        if (tid < ADIM / 4) ((float4*)s_h)[tid] = ((const float4*)hg)[tid];
    }

    // ---- (row, col) tables for triu_indices(F, k=1) ----
    if (tid < FNUM - 1) {
        int r    = tid;
        int base = r * (FNUM - 1) - (r * (r - 1)) / 2;
        int cnt  = FNUM - 1 - r;
        for (int k = 0; k < cnt; ++k) {
            s_row[base + k] = (unsigned char)r;
            s_col[base + k] = (unsigned char)(r + 1 + k);
        }
    }

    // p_vec in registers
    const float4 pv0 = ((const float4*)pvg)[0];
    const float4 pv1 = ((const float4*)pvg)[1];
    const float4 pv2 = ((const float4*)pvg)[2];
    const float4 pv3 = ((const float4*)pvg)[3];

    __syncthreads();

    // Fixed per-thread A-half: even lanes -> cols 0..15, odd -> 16..31.
    const int half = tid & 1;
    const float2* h2 = (const float2*)(s_h + 16 * half);
    const int woff = 16 * half;

    #pragma unroll 1
    for (int it = 0; it < NIT; ++it) {
        const int task  = it * TPB + tid;
        const int valid = (task < NT);
        const int p     = valid ? (task >> 1) : 0;

        const int r = s_row[p];
        const int c = s_col[p];
        const float4* er = (const float4*)(s_e + r * DDIM);
        const float4* ec = (const float4*)(s_e + c * DDIM);
        const float4 e0 = er[0], e1 = er[1], e2 = er[2], e3 = er[3];
        const float4 f0 = ec[0], f1 = ec[1], f2 = ec[2], f3 = ec[3];

        float x[16];
        x[0]  = e0.x * f0.x;  x[1]  = e0.y * f0.y;  x[2]  = e0.z * f0.z;  x[3]  = e0.w * f0.w;
        x[4]  = e1.x * f1.x;  x[5]  = e1.y * f1.y;  x[6]  = e1.z * f1.z;  x[7]  = e1.w * f1.w;
        x[8]  = e2.x * f2.x;  x[9]  = e2.y * f2.y;  x[10] = e2.z * f2.z;  x[11] = e2.w * f2.w;
        x[12] = e3.x * f3.x;  x[13] = e3.y * f3.y;  x[14] = e3.z * f3.z;  x[15] = e3.w * f3.w;

        // Partial t: even lanes sum d 0..7, odd lanes d 8..15 (combined via shfl).
        float tpart;
        if (half == 0) {
            float ta = x[0] * pv0.x;  ta = fmaf(x[1], pv0.y, ta);
            ta = fmaf(x[2], pv0.z, ta);  ta = fmaf(x[3], pv0.w, ta);
            float tb = x[4] * pv1.x;  tb = fmaf(x[5], pv1.y, tb);
            tb = fmaf(x[6], pv1.z, tb);  tb = fmaf(x[7], pv1.w, tb);
            tpart = ta + tb;
        } else {
            float tc = x[8] * pv2.x;  tc = fmaf(x[9],  pv2.y, tc);
            tc = fmaf(x[10], pv2.z, tc);  tc = fmaf(x[11], pv2.w, tc);
            float td = x[12] * pv3.x; td = fmaf(x[13], pv3.y, td);
            td = fmaf(x[14], pv3.z, td);  td = fmaf(x[15], pv3.w, td);
            tpart = tc + td;
        }

        // 16 A-columns for this half: acc[k] covers a = woff + {2k, 2k+1}
        unsigned long long acc[8];
        #pragma unroll
        for (int k = 0; k < 8; ++k) acc[k] = 0ULL;

        #pragma unroll
        for (int d = 0; d < 16; ++d) {
            const unsigned long long xd = pk2(x[d], x[d]);
            const ulonglong2* wr = (const ulonglong2*)(s_W + d * ADIM + woff);
            ulonglong2 wa = wr[0];
            ulonglong2 wb = wr[1];
            ulonglong2 wc = wr[2];
            ulonglong2 wd_ = wr[3];
            acc[0] = fma2(xd, wa.x, acc[0]);
            acc[1] = fma2(xd, wa.y, acc[1]);
            acc[2] = fma2(xd, wb.x, acc[2]);
            acc[3] = fma2(xd, wb.y, acc[3]);
            acc[4] = fma2(xd, wc.x, acc[4]);
            acc[5] = fma2(xd, wc.y, acc[5]);
            acc[6] = fma2(xd, wd_.x, acc[6]);
            acc[7] = fma2(xd, wd_.y, acc[7]);
        }

        // relu + dot with h-half (2 independent chains)
        float s0 = 0.f, s1 = 0.f;
        #pragma unroll
        for (int k = 0; k < 8; ++k) {
            float2 v  = upk2(acc[k]);
            float2 hh = h2[k];
            float r0 = fmaxf(v.x, 0.f);
            float r1 = fmaxf(v.y, 0.f);
            s0 = fmaf(r0, hh.x, s0);
            s1 = fmaf(r1, hh.y, s1);
        }
        float spart = s0 + s1;

        // Combine halves with partner lane (tid^1): same pair by construction.
        float so = __shfl_xor_sync(0xffffffffu, spart, 1);
        float to = __shfl_xor_sync(0xffffffffu, tpart, 1);
        if (valid && half == 0) {
            s_score[p] = spart + so;
            s_t[p]     = tpart + to;
        }
    }

    __syncthreads();

    // ---- fused softmax reduction: out[b] = sum(e*t) / sum(e) ----
    const int lane = tid & 31;
    const int wid  = tid >> 5;

    float m = -3.4e38f;
    for (int p = tid; p < NP; p += TPB) m = fmaxf(m, s_score[p]);
    #pragma unroll
    for (int o = 16; o > 0; o >>= 1) m = fmaxf(m, __shfl_xor_sync(0xffffffffu, m, o));
    if (lane == 0) s_red[wid] = m;
    __syncthreads();

    float mm = s_red[0];
    #pragma unroll
    for (int i = 1; i < 8; ++i) mm = fmaxf(mm, s_red[i]);

    float se = 0.f, st = 0.f;
    for (int p = tid; p < NP; p += TPB) {
        float e = __expf(s_score[p] - mm);
        se += e;
        st = fmaf(e, s_t[p], st);
    }
    #pragma unroll
    for (int o = 16; o > 0; o >>= 1) {
        se += __shfl_xor_sync(0xffffffffu, se, o);
        st += __shfl_xor_sync(0xffffffffu, st, o);
    }
    if (lane == 0) { s_red[8 + wid] = se; s_red[16 + wid] = st; }
    __syncthreads();

    if (tid == 0) {
        float SE = 0.f, ST = 0.f;
        #pragma unroll
        for (int i = 0; i < 8; ++i) { SE += s_red[8 + i]; ST += s_red[16 + i]; }
        out[b] = ST / SE;
    }
}

extern "C" void kernel_launch(void* const* d_in, const int* in_sizes, int n_in,
                              void* d_out, int out_size) {
    const float* feat = (const float*)d_in[0];   // [B, 50, 16]
    const float* W    = (const float*)d_in[1];   // [16, 32]
    const float* h    = (const float*)d_in[2];   // [32]
    const float* pv   = (const float*)d_in[3];   // [16]
    float* out        = (float*)d_out;           // [B, 1]

    const int B = in_sizes[0] / (FNUM * DDIM);   // 4096
    afm_kernel<<<B, TPB>>>(feat, W, h, pv, out);
}

// round 3
// speedup vs baseline: 2.3674x; 2.3674x over previous
#include <cuda_runtime.h>

#define FNUM 50
#define DDIM 16
#define ADIM 32
#define NP   1225                 // F*(F-1)/2
#define TPB  256
#define ESTR 20                   // padded row stride (floats) for s_e, 16B-aligned, bank-safe
#define NG   ((NP + 3) / 4)       // 307 pair-groups of 4 (one octet each)

typedef unsigned long long u64;

// ---- packed f32x2 helpers (ptxas never emits f32x2 from C++; inline PTX) ----
__device__ __forceinline__ u64 pk2(float lo, float hi) {
    u64 r;
    asm("mov.b64 %0, {%1, %2};" : "=l"(r) : "f"(lo), "f"(hi));
    return r;
}
__device__ __forceinline__ u64 mul2(u64 a, u64 b) {
    u64 d;
    asm("mul.rn.f32x2 %0, %1, %2;" : "=l"(d) : "l"(a), "l"(b));
    return d;
}
__device__ __forceinline__ u64 fma2(u64 a, u64 b, u64 c) {
    u64 d;
    asm("fma.rn.f32x2 %0, %1, %2, %3;" : "=l"(d) : "l"(a), "l"(b), "l"(c));
    return d;
}
__device__ __forceinline__ float2 upk2(u64 v) {
    float lo, hi;
    asm("mov.b64 {%0, %1}, %2;" : "=f"(lo), "=f"(hi) : "l"(v));
    return make_float2(lo, hi);
}

__global__ __launch_bounds__(TPB, 2) void afm_kernel(
    const float* __restrict__ feat,   // [B, F, D]
    const float* __restrict__ Wg,     // [D, A] row-major
    const float* __restrict__ hg,     // [A]
    const float* __restrict__ pvg,    // [D]
    float* __restrict__ out)          // [B]
{
    __shared__ __align__(16) float s_e[FNUM * ESTR];       // padded feature tile
    __shared__ __align__(16) u64   s_Wt[ADIM][DDIM / 2];   // Wt[col][dd] = {W[2dd][col], W[2dd+1][col]}
    __shared__ __align__(16) float s_h[ADIM];
    __shared__ __align__(16) u64   s_pv[DDIM / 2];         // pv packed along d
    __shared__ float s_score[NP];
    __shared__ float s_t[NP];
    __shared__ unsigned char s_row[NP];
    __shared__ unsigned char s_col[NP];
    __shared__ float s_red[24];

    const int tid  = threadIdx.x;
    const int b    = blockIdx.x;
    const int lane = tid & 31;
    const int wid  = tid >> 5;
    const int oct  = (lane >> 3);     // 0..3 : which pair in the group
    const int sub  = lane & 7;        // 0..7 : which 4-column slice of A

    // ---- cooperative SMEM fill ----
    {
        const float* src = feat + (size_t)b * (FNUM * DDIM);
        #pragma unroll 1
        for (int i = tid; i < FNUM * DDIM; i += TPB) {
            int r = i >> 4, d = i & 15;
            s_e[r * ESTR + d] = src[i];
        }
        // W transposed+packed: one u64 per thread (256 = 32 cols * 8 dd)
        {
            int col = tid >> 3, dd = tid & 7;
            float lo = Wg[(2 * dd) * ADIM + col];
            float hi = Wg[(2 * dd + 1) * ADIM + col];
            s_Wt[col][dd] = pk2(lo, hi);
        }
        if (tid < ADIM) s_h[tid] = hg[tid];
        if (tid < DDIM / 2) s_pv[tid] = pk2(pvg[2 * tid], pvg[2 * tid + 1]);
    }

    // (row, col) tables for triu_indices(F, k=1)
    if (tid < FNUM - 1) {
        int r    = tid;
        int base = r * (FNUM - 1) - (r * (r - 1)) / 2;
        int cnt  = FNUM - 1 - r;
        for (int k = 0; k < cnt; ++k) {
            s_row[base + k] = (unsigned char)r;
            s_col[base + k] = (unsigned char)(r + 1 + k);
        }
    }
    __syncthreads();

    // ---- per-thread resident W slice (4 cols x 8 dd = 32 u64) + h slice ----
    u64 w0[8], w1[8], w2[8], w3[8];
    #pragma unroll
    for (int k = 0; k < 8; ++k) {
        w0[k] = s_Wt[4 * sub + 0][k];
        w1[k] = s_Wt[4 * sub + 1][k];
        w2[k] = s_Wt[4 * sub + 2][k];
        w3[k] = s_Wt[4 * sub + 3][k];
    }
    const float h0 = s_h[4 * sub + 0];
    const float h1 = s_h[4 * sub + 1];
    const float h2 = s_h[4 * sub + 2];
    const float h3 = s_h[4 * sub + 3];

    // ---- main loop: each warp-iteration processes 4 pairs (one per octet) ----
    #pragma unroll 1
    for (int g = wid; g < NG; g += TPB / 32) {
        const int p4 = g * 4 + oct;
        const int p  = (p4 < NP) ? p4 : NP - 1;

        const int r = s_row[p];
        const int c = s_col[p];
        const ulonglong2* er = (const ulonglong2*)(s_e + r * ESTR);
        const ulonglong2* ec = (const ulonglong2*)(s_e + c * ESTR);

        u64 x2[8];
        {
            ulonglong2 ra = er[0], rb = er[1], rc = er[2], rd = er[3];
            ulonglong2 ca = ec[0], cb = ec[1], cc = ec[2], cd = ec[3];
            x2[0] = mul2(ra.x, ca.x);  x2[1] = mul2(ra.y, ca.y);
            x2[2] = mul2(rb.x, cb.x);  x2[3] = mul2(rb.y, cb.y);
            x2[4] = mul2(rc.x, cc.x);  x2[5] = mul2(rc.y, cc.y);
            x2[6] = mul2(rd.x, cd.x);  x2[7] = mul2(rd.y, cd.y);
        }

        u64 a0 = 0ULL, a1 = 0ULL, a2 = 0ULL, a3 = 0ULL, aT = 0ULL;
        #pragma unroll
        for (int k = 0; k < 8; ++k) {
            a0 = fma2(x2[k], w0[k], a0);
            a1 = fma2(x2[k], w1[k], a1);
            a2 = fma2(x2[k], w2[k], a2);
            a3 = fma2(x2[k], w3[k], a3);
            aT = fma2(x2[k], s_pv[k], aT);   // broadcast LDS.64, 1 wavefront
        }

        // epilogue: column sums (lo+hi), relu, dot with h
        float2 v0 = upk2(a0), v1 = upk2(a1), v2 = upk2(a2), v3 = upk2(a3);
        float s;
        s = fmaxf(v0.x + v0.y, 0.f) * h0;
        s = fmaf(fmaxf(v1.x + v1.y, 0.f), h1, s);
        s = fmaf(fmaxf(v2.x + v2.y, 0.f), h2, s);
        s = fmaf(fmaxf(v3.x + v3.y, 0.f), h3, s);

        float2 vt = upk2(aT);
        const float t = vt.x + vt.y;      // identical across octet lanes

        // octet reduction of s (offsets 1,2,4 stay inside the octet)
        s += __shfl_xor_sync(0xffffffffu, s, 1);
        s += __shfl_xor_sync(0xffffffffu, s, 2);
        s += __shfl_xor_sync(0xffffffffu, s, 4);

        if (sub == 0 && p4 < NP) {
            s_score[p4] = s;
            s_t[p4]     = t;
        }
    }

    __syncthreads();

    // ---- fused softmax reduction: out[b] = sum(e*t) / sum(e) ----
    float m = -3.4e38f;
    for (int p = tid; p < NP; p += TPB) m = fmaxf(m, s_score[p]);
    #pragma unroll
    for (int o = 16; o > 0; o >>= 1) m = fmaxf(m, __shfl_xor_sync(0xffffffffu, m, o));
    if (lane == 0) s_red[wid] = m;
    __syncthreads();

    float mm = s_red[0];
    #pragma unroll
    for (int i = 1; i < 8; ++i) mm = fmaxf(mm, s_red[i]);

    float se = 0.f, st = 0.f;
    for (int p = tid; p < NP; p += TPB) {
        float e = __expf(s_score[p] - mm);
        se += e;
        st = fmaf(e, s_t[p], st);
    }
    #pragma unroll
    for (int o = 16; o > 0; o >>= 1) {
        se += __shfl_xor_sync(0xffffffffu, se, o);
        st += __shfl_xor_sync(0xffffffffu, st, o);
    }
    if (lane == 0) { s_red[8 + wid] = se; s_red[16 + wid] = st; }
    __syncthreads();

    if (tid == 0) {
        float SE = 0.f, ST = 0.f;
        #pragma unroll
        for (int i = 0; i < 8; ++i) { SE += s_red[8 + i]; ST += s_red[16 + i]; }
        out[b] = ST / SE;
    }
}

extern "C" void kernel_launch(void* const* d_in, const int* in_sizes, int n_in,
                              void* d_out, int out_size) {
    const float* feat = (const float*)d_in[0];   // [B, 50, 16]
    const float* W    = (const float*)d_in[1];   // [16, 32]
    const float* h    = (const float*)d_in[2];   // [32]
    const float* pv   = (const float*)d_in[3];   // [16]
    float* out        = (float*)d_out;           // [B, 1]

    const int B = in_sizes[0] / (FNUM * DDIM);   // 4096
    afm_kernel<<<B, TPB>>>(feat, W, h, pv, out);
}

// round 6
// speedup vs baseline: 5.0290x; 2.1243x over previous
#include <cuda_runtime.h>
#include <cstdint>

#define FNUM 50
#define DDIM 16
#define ADIM 32
#define NP   1225
#define NPAD 1232                // 77 tiles of 16
#define MT   77
#define TPB  256
#define ESTR 17                  // padded e-row stride (floats), spreads banks

typedef unsigned int u32;

__device__ __forceinline__ u32 to_tf32(float x) {
    u32 r;
    asm("cvt.rna.tf32.f32 %0, %1;" : "=r"(r) : "f"(x));
    return r;
}
__device__ __forceinline__ void split_tf32(float x, u32& hi, u32& lo) {
    hi = to_tf32(x);
    lo = to_tf32(x - __uint_as_float(hi));
}
__device__ __forceinline__ void mma_tf32(float* c, const u32* a, const u32* b) {
    asm volatile(
        "mma.sync.aligned.m16n8k8.row.col.f32.tf32.tf32.f32 "
        "{%0,%1,%2,%3}, {%4,%5,%6,%7}, {%8,%9}, {%0,%1,%2,%3};"
        : "+f"(c[0]), "+f"(c[1]), "+f"(c[2]), "+f"(c[3])
        : "r"(a[0]), "r"(a[1]), "r"(a[2]), "r"(a[3]), "r"(b[0]), "r"(b[1]));
}

__global__ __launch_bounds__(TPB) void afm_kernel(
    const float* __restrict__ feat,   // [B, F, D]
    const float* __restrict__ Wg,     // [D, A] row-major
    const float* __restrict__ hg,     // [A]
    const float* __restrict__ pvg,    // [D]
    float* __restrict__ out)          // [B]
{
    __shared__ __align__(16) float s_e[FNUM * ESTR];
    __shared__ float s_score[NP];
    __shared__ float s_t[NP];
    __shared__ unsigned char s_row[NPAD];
    __shared__ unsigned char s_col[NPAD];
    __shared__ float s_red[24];

    const int tid  = threadIdx.x;
    const int b    = blockIdx.x;
    const int lane = tid & 31;
    const int wid  = tid >> 5;
    const int g    = lane >> 2;      // group id 0..7  (row within tile / B col)
    const int m    = lane & 3;       // thread-in-group (A col / C col pair)

    // ---- SMEM fill: features (padded stride), triu tables ----
    {
        const float* src = feat + (size_t)b * (FNUM * DDIM);
        #pragma unroll 1
        for (int i = tid; i < FNUM * DDIM; i += TPB) {
            int r = i >> 4, d = i & 15;
            s_e[r * ESTR + d] = src[i];
        }
    }
    if (tid < FNUM - 1) {
        int r    = tid;
        int base = r * (FNUM - 1) - (r * (r - 1)) / 2;
        int cnt  = FNUM - 1 - r;
        for (int k = 0; k < cnt; ++k) {
            s_row[base + k] = (unsigned char)r;
            s_col[base + k] = (unsigned char)(r + 1 + k);
        }
    }
    if (tid < NPAD - NP) {           // pad tail with valid indices
        s_row[NP + tid] = 0;
        s_col[NP + tid] = 1;
    }

    // ---- B fragments in registers: Bext[16, 40] = [W | pv | 0] ----
    // frag (nt, kt): b0 = Bext[kt*8+m][nt*8+g], b1 = Bext[kt*8+m+4][nt*8+g]
    u32 bh[5][2][2], bl[5][2][2];
    #pragma unroll
    for (int nt = 0; nt < 5; ++nt) {
        const int n = nt * 8 + g;
        #pragma unroll
        for (int kt = 0; kt < 2; ++kt) {
            const int d0 = kt * 8 + m;
            const int d1 = d0 + 4;
            float v0, v1;
            if (nt < 4)       { v0 = Wg[d0 * ADIM + n]; v1 = Wg[d1 * ADIM + n]; }
            else if (g == 0)  { v0 = pvg[d0];           v1 = pvg[d1]; }
            else              { v0 = 0.f;               v1 = 0.f; }
            split_tf32(v0, bh[nt][kt][0], bl[nt][kt][0]);
            split_tf32(v1, bh[nt][kt][1], bl[nt][kt][1]);
        }
    }
    // h slice for epilogue: cols nt*8 + 2m, +1
    float hreg[8];
    #pragma unroll
    for (int nt = 0; nt < 4; ++nt) {
        hreg[2 * nt]     = hg[nt * 8 + 2 * m];
        hreg[2 * nt + 1] = hg[nt * 8 + 2 * m + 1];
    }
    __syncthreads();

    // ---- main loop: one M-tile (16 pairs) per warp-iteration ----
    #pragma unroll 1
    for (int mt = wid; mt < MT; mt += TPB / 32) {
        const int p0 = mt * 16 + g;
        const int p1 = p0 + 8;
        const int r0 = s_row[p0], q0 = s_col[p0];
        const int r1 = s_row[p1], q1 = s_col[p1];
        const float* E0 = s_e + r0 * ESTR;
        const float* F0 = s_e + q0 * ESTR;
        const float* E1 = s_e + r1 * ESTR;
        const float* F1 = s_e + q1 * ESTR;

        // A fragments: rows p0/p1, cols m, m+4, m+8, m+12
        u32 ah[2][4], al[2][4];
        #pragma unroll
        for (int kt = 0; kt < 2; ++kt) {
            const int c0 = kt * 8 + m;
            const int c1 = c0 + 4;
            split_tf32(E0[c0] * F0[c0], ah[kt][0], al[kt][0]);
            split_tf32(E1[c0] * F1[c0], ah[kt][1], al[kt][1]);
            split_tf32(E0[c1] * F0[c1], ah[kt][2], al[kt][2]);
            split_tf32(E1[c1] * F1[c1], ah[kt][3], al[kt][3]);
        }

        float acc[5][4];
        #pragma unroll
        for (int nt = 0; nt < 5; ++nt) {
            acc[nt][0] = 0.f; acc[nt][1] = 0.f; acc[nt][2] = 0.f; acc[nt][3] = 0.f;
        }

        // 3-pass split product: hi*hi + hi*lo + lo*hi  (lo*lo ~2^-22, dropped)
        #pragma unroll
        for (int kt = 0; kt < 2; ++kt) {
            #pragma unroll
            for (int nt = 0; nt < 5; ++nt) mma_tf32(acc[nt], ah[kt], bh[nt][kt][0] == 0 && false ? bh[nt][kt] : bh[nt][kt]);
            #pragma unroll
            for (int nt = 0; nt < 5; ++nt) mma_tf32(acc[nt], ah[kt], bl[nt][kt]);
            #pragma unroll
            for (int nt = 0; nt < 5; ++nt) mma_tf32(acc[nt], al[kt], bh[nt][kt]);
        }

        // epilogue: relu + h-dot over cols<32; col 32 (nt=4, m==0, elem 0/2) is t
        float s0 = 0.f, s1 = 0.f;
        #pragma unroll
        for (int nt = 0; nt < 4; ++nt) {
            s0 = fmaf(fmaxf(acc[nt][0], 0.f), hreg[2 * nt],     s0);
            s0 = fmaf(fmaxf(acc[nt][1], 0.f), hreg[2 * nt + 1], s0);
            s1 = fmaf(fmaxf(acc[nt][2], 0.f), hreg[2 * nt],     s1);
            s1 = fmaf(fmaxf(acc[nt][3], 0.f), hreg[2 * nt + 1], s1);
        }
        const float t0 = acc[4][0];   // col 32 when m==0
        const float t1 = acc[4][2];

        // quad reduction (cols live in lanes of same group)
        s0 += __shfl_xor_sync(0xffffffffu, s0, 1);
        s0 += __shfl_xor_sync(0xffffffffu, s0, 2);
        s1 += __shfl_xor_sync(0xffffffffu, s1, 1);
        s1 += __shfl_xor_sync(0xffffffffu, s1, 2);

        if (m == 0) {
            if (p0 < NP) { s_score[p0] = s0; s_t[p0] = t0; }
            if (p1 < NP) { s_score[p1] = s1; s_t[p1] = t1; }
        }
    }

    __syncthreads();

    // ---- fused softmax reduction: out[b] = sum(e*t) / sum(e) ----
    float mx = -3.4e38f;
    for (int p = tid; p < NP; p += TPB) mx = fmaxf(mx, s_score[p]);
    #pragma unroll
    for (int o = 16; o > 0; o >>= 1) mx = fmaxf(mx, __shfl_xor_sync(0xffffffffu, mx, o));
    if (lane == 0) s_red[wid] = mx;
    __syncthreads();

    float mm = s_red[0];
    #pragma unroll
    for (int i = 1; i < 8; ++i) mm = fmaxf(mm, s_red[i]);

    float se = 0.f, st = 0.f;
    for (int p = tid; p < NP; p += TPB) {
        float e = __expf(s_score[p] - mm);
        se += e;
        st = fmaf(e, s_t[p], st);
    }
    #pragma unroll
    for (int o = 16; o > 0; o >>= 1) {
        se += __shfl_xor_sync(0xffffffffu, se, o);
        st += __shfl_xor_sync(0xffffffffu, st, o);
    }
    if (lane == 0) { s_red[8 + wid] = se; s_red[16 + wid] = st; }
    __syncthreads();

    if (tid == 0) {
        float SE = 0.f, ST = 0.f;
        #pragma unroll
        for (int i = 0; i < 8; ++i) { SE += s_red[8 + i]; ST += s_red[16 + i]; }
        out[b] = ST / SE;
    }
}

extern "C" void kernel_launch(void* const* d_in, const int* in_sizes, int n_in,
                              void* d_out, int out_size) {
    const float* feat = (const float*)d_in[0];   // [B, 50, 16]
    const float* W    = (const float*)d_in[1];   // [16, 32]
    const float* h    = (const float*)d_in[2];   // [32]
    const float* pv   = (const float*)d_in[3];   // [16]
    float* out        = (float*)d_out;           // [B, 1]

    const int B = in_sizes[0] / (FNUM * DDIM);   // 4096
    afm_kernel<<<B, TPB>>>(feat, W, h, pv, out);
}

// round 7
// speedup vs baseline: 5.9464x; 1.1824x over previous
#include <cuda_runtime.h>
#include <cstdint>

#define FNUM 50
#define DDIM 16
#define ADIM 32
#define NP   1225
#define NPAD 1232                // 77 tiles of 16
#define MT   77
#define TPB  256
#define ESTR 17                  // padded e-row stride (floats), spreads banks

typedef unsigned int u32;

// tf32 "split" via truncation: hi = x with low 13 mantissa bits zeroed (valid
// tf32 pattern), r = x - hi is exact (Sterbenz), lo = trunc(r). Error ~2^-22.
__device__ __forceinline__ void split_mask(float x, u32& hi, u32& lo) {
    u32 xb = __float_as_uint(x);
    hi = xb & 0xFFFFE000u;
    float r = x - __uint_as_float(hi);
    lo = __float_as_uint(r) & 0xFFFFE000u;
}
__device__ __forceinline__ void mma_tf32(float* c, const u32* a, const u32* b) {
    asm volatile(
        "mma.sync.aligned.m16n8k8.row.col.f32.tf32.tf32.f32 "
        "{%0,%1,%2,%3}, {%4,%5,%6,%7}, {%8,%9}, {%0,%1,%2,%3};"
        : "+f"(c[0]), "+f"(c[1]), "+f"(c[2]), "+f"(c[3])
        : "r"(a[0]), "r"(a[1]), "r"(a[2]), "r"(a[3]), "r"(b[0]), "r"(b[1]));
}

__global__ __launch_bounds__(TPB) void afm_kernel(
    const float* __restrict__ feat,   // [B, F, D]
    const float* __restrict__ Wg,     // [D, A] row-major
    const float* __restrict__ hg,     // [A]
    const float* __restrict__ pvg,    // [D]
    float* __restrict__ out)          // [B]
{
    __shared__ __align__(16) float s_e[FNUM * ESTR];
    __shared__ float s_score[NP];
    __shared__ float s_t[NP];
    __shared__ unsigned char s_row[NPAD];
    __shared__ unsigned char s_col[NPAD];
    __shared__ float s_red[24];

    const int tid  = threadIdx.x;
    const int b    = blockIdx.x;
    const int lane = tid & 31;
    const int wid  = tid >> 5;
    const int g    = lane >> 2;      // group id 0..7  (A/C row, B col)
    const int m    = lane & 3;       // thread-in-group (A col, B row)

    // ---- SMEM fill: features (padded stride), triu tables ----
    {
        const float* src = feat + (size_t)b * (FNUM * DDIM);
        #pragma unroll 1
        for (int i = tid; i < FNUM * DDIM; i += TPB) {
            int r = i >> 4, d = i & 15;
            s_e[r * ESTR + d] = src[i];
        }
    }
    if (tid < FNUM - 1) {
        int r    = tid;
        int base = r * (FNUM - 1) - (r * (r - 1)) / 2;
        int cnt  = FNUM - 1 - r;
        for (int k = 0; k < cnt; ++k) {
            s_row[base + k] = (unsigned char)r;
            s_col[base + k] = (unsigned char)(r + 1 + k);
        }
    }
    if (tid < NPAD - NP) {           // pad tail with valid indices
        s_row[NP + tid] = 0;
        s_col[NP + tid] = 1;
    }

    // ---- B fragments in registers: W[16, 32], 4 N-tiles ----
    // frag (nt, kt): b0 = W[kt*8+m][nt*8+g], b1 = W[kt*8+m+4][nt*8+g]
    u32 bh[4][2][2], bl[4][2][2];
    #pragma unroll
    for (int nt = 0; nt < 4; ++nt) {
        const int n = nt * 8 + g;
        #pragma unroll
        for (int kt = 0; kt < 2; ++kt) {
            const int d0 = kt * 8 + m;
            const int d1 = d0 + 4;
            split_mask(Wg[d0 * ADIM + n], bh[nt][kt][0], bl[nt][kt][0]);
            split_mask(Wg[d1 * ADIM + n], bh[nt][kt][1], bl[nt][kt][1]);
        }
    }
    // h slice for epilogue: cols nt*8 + 2m, +1
    float hreg[8];
    #pragma unroll
    for (int nt = 0; nt < 4; ++nt) {
        hreg[2 * nt]     = hg[nt * 8 + 2 * m];
        hreg[2 * nt + 1] = hg[nt * 8 + 2 * m + 1];
    }
    // p_vec slice for scalar t: d = m, m+4, m+8, m+12
    float pvr[4];
    #pragma unroll
    for (int k = 0; k < 4; ++k) pvr[k] = pvg[m + 4 * k];
    __syncthreads();

    // ---- main loop: one M-tile (16 pairs) per warp-iteration ----
    #pragma unroll 1
    for (int mt = wid; mt < MT; mt += TPB / 32) {
        const int p0 = mt * 16 + g;
        const int p1 = p0 + 8;
        const int r0 = s_row[p0], q0 = s_col[p0];
        const int r1 = s_row[p1], q1 = s_col[p1];
        const float* E0 = s_e + r0 * ESTR;
        const float* F0 = s_e + q0 * ESTR;
        const float* E1 = s_e + r1 * ESTR;
        const float* F1 = s_e + q1 * ESTR;

        // raw products for this thread's A-columns: d = m, m+4, m+8, m+12
        float x0[4], x1[4];          // [k]: d = m + 4k, rows p0 / p1
        #pragma unroll
        for (int k = 0; k < 4; ++k) {
            const int d = m + 4 * k;
            x0[k] = E0[d] * F0[d];
            x1[k] = E1[d] * F1[d];
        }

        // A fragments (kt selects d-half): a0=row p0 col kt*8+m, a1=row p1,
        // a2=row p0 col kt*8+m+4, a3=row p1
        u32 ah[2][4], al[2][4];
        split_mask(x0[0], ah[0][0], al[0][0]);
        split_mask(x1[0], ah[0][1], al[0][1]);
        split_mask(x0[1], ah[0][2], al[0][2]);
        split_mask(x1[1], ah[0][3], al[0][3]);
        split_mask(x0[2], ah[1][0], al[1][0]);
        split_mask(x1[2], ah[1][1], al[1][1]);
        split_mask(x0[3], ah[1][2], al[1][2]);
        split_mask(x1[3], ah[1][3], al[1][3]);

        float acc[4][4];
        #pragma unroll
        for (int nt = 0; nt < 4; ++nt) {
            acc[nt][0] = 0.f; acc[nt][1] = 0.f; acc[nt][2] = 0.f; acc[nt][3] = 0.f;
        }

        // 3-pass split product: hi*hi + hi*lo + lo*hi  (lo*lo ~2^-22, dropped)
        #pragma unroll
        for (int kt = 0; kt < 2; ++kt) {
            #pragma unroll
            for (int nt = 0; nt < 4; ++nt) mma_tf32(acc[nt], ah[kt], bh[nt][kt]);
            #pragma unroll
            for (int nt = 0; nt < 4; ++nt) mma_tf32(acc[nt], ah[kt], bl[nt][kt]);
            #pragma unroll
            for (int nt = 0; nt < 4; ++nt) mma_tf32(acc[nt], al[kt], bh[nt][kt]);
        }

        // scalar t partials (full fp32): t_p = sum_d x[p][d] * pv[d]
        float t0 = x0[0] * pvr[0];
        t0 = fmaf(x0[1], pvr[1], t0);
        t0 = fmaf(x0[2], pvr[2], t0);
        t0 = fmaf(x0[3], pvr[3], t0);
        float t1 = x1[0] * pvr[0];
        t1 = fmaf(x1[1], pvr[1], t1);
        t1 = fmaf(x1[2], pvr[2], t1);
        t1 = fmaf(x1[3], pvr[3], t1);

        // epilogue: relu + h-dot
        float s0 = 0.f, s1 = 0.f;
        #pragma unroll
        for (int nt = 0; nt < 4; ++nt) {
            s0 = fmaf(fmaxf(acc[nt][0], 0.f), hreg[2 * nt],     s0);
            s0 = fmaf(fmaxf(acc[nt][1], 0.f), hreg[2 * nt + 1], s0);
            s1 = fmaf(fmaxf(acc[nt][2], 0.f), hreg[2 * nt],     s1);
            s1 = fmaf(fmaxf(acc[nt][3], 0.f), hreg[2 * nt + 1], s1);
        }

        // quad reductions (over m = lanes 1,2 apart)
        s0 += __shfl_xor_sync(0xffffffffu, s0, 1);
        s0 += __shfl_xor_sync(0xffffffffu, s0, 2);
        s1 += __shfl_xor_sync(0xffffffffu, s1, 1);
        s1 += __shfl_xor_sync(0xffffffffu, s1, 2);
        t0 += __shfl_xor_sync(0xffffffffu, t0, 1);
        t0 += __shfl_xor_sync(0xffffffffu, t0, 2);
        t1 += __shfl_xor_sync(0xffffffffu, t1, 1);
        t1 += __shfl_xor_sync(0xffffffffu, t1, 2);

        if (m == 0) {
            if (p0 < NP) { s_score[p0] = s0; s_t[p0] = t0; }
            if (p1 < NP) { s_score[p1] = s1; s_t[p1] = t1; }
        }
    }

    __syncthreads();

    // ---- fused softmax reduction: out[b] = sum(e*t) / sum(e) ----
    float mx = -3.4e38f;
    for (int p = tid; p < NP; p += TPB) mx = fmaxf(mx, s_score[p]);
    #pragma unroll
    for (int o = 16; o > 0; o >>= 1) mx = fmaxf(mx, __shfl_xor_sync(0xffffffffu, mx, o));
    if (lane == 0) s_red[wid] = mx;
    __syncthreads();

    float mm = s_red[0];
    #pragma unroll
    for (int i = 1; i < 8; ++i) mm = fmaxf(mm, s_red[i]);

    float se = 0.f, st = 0.f;
    for (int p = tid; p < NP; p += TPB) {
        float e = __expf(s_score[p] - mm);
        se += e;
        st = fmaf(e, s_t[p], st);
    }
    #pragma unroll
    for (int o = 16; o > 0; o >>= 1) {
        se += __shfl_xor_sync(0xffffffffu, se, o);
        st += __shfl_xor_sync(0xffffffffu, st, o);
    }
    if (lane == 0) { s_red[8 + wid] = se; s_red[16 + wid] = st; }
    __syncthreads();

    if (tid == 0) {
        float SE = 0.f, ST = 0.f;
        #pragma unroll
        for (int i = 0; i < 8; ++i) { SE += s_red[8 + i]; ST += s_red[16 + i]; }
        out[b] = ST / SE;
    }
}

extern "C" void kernel_launch(void* const* d_in, const int* in_sizes, int n_in,
                              void* d_out, int out_size) {
    const float* feat = (const float*)d_in[0];   // [B, 50, 16]
    const float* W    = (const float*)d_in[1];   // [16, 32]
    const float* h    = (const float*)d_in[2];   // [32]
    const float* pv   = (const float*)d_in[3];   // [16]
    float* out        = (float*)d_out;           // [B, 1]

    const int B = in_sizes[0] / (FNUM * DDIM);   // 4096
    afm_kernel<<<B, TPB>>>(feat, W, h, pv, out);
}